// round 5
// baseline (speedup 1.0000x reference)
#include <cuda_runtime.h>
#include <math.h>

#define HW 64
#define NP 4096
#define CHUNK 2048
#define MAXB 32

// scratch: [batch][arr(0=g,1=bnd)][4096] — two sorted ascending 2048-chunks per array
__device__ __align__(16) float g_scr[2 * MAXB * NP];
// monotonically-increasing grid barrier ticket counter (never reset; replay-safe)
__device__ unsigned int g_bar;

__global__ __launch_bounds__(1024, 1)
void chamfer_fused_kernel(const float* __restrict__ depth,
                          const float* __restrict__ bnd,
                          float* __restrict__ out,
                          float inv_total) {
    __shared__ float sT[NP];     // sort: first 2048 used; query: full 4096 target
    __shared__ float swarp[32];
    const int t   = threadIdx.x;
    const int blk = blockIdx.x;
    const int c   = blk & 1;          // chunk within array
    const int arr = (blk >> 1) & 1;   // 0 = sobel(g), 1 = boundary
    const int b   = blk >> 2;         // batch
    const unsigned int nblk = gridDim.x;

    if (blk == 0 && t == 0) out[0] = 0.0f;   // all adds happen after the barrier

    const int i  = 2 * t;             // element index within chunk
    const int e0 = c * CHUNK + i;     // element index within batch array

    // ---- Phase 1: produce this block's 2048 values ----
    float v0, v1;
    if (arr == 1) {
        float2 q = *(const float2*)(bnd + b * NP + e0);
        v0 = q.x; v1 = q.y;
    } else {
        const float* d = depth + b * NP;
        #pragma unroll
        for (int m = 0; m < 2; m++) {
            int e = e0 + m;
            int y = e >> 6, x = e & 63;
            float p[3][3];
            #pragma unroll
            for (int dy = -1; dy <= 1; dy++)
                #pragma unroll
                for (int dx = -1; dx <= 1; dx++) {
                    int yy = y + dy, xx = x + dx;
                    bool ok = (yy >= 0) & (yy < HW) & (xx >= 0) & (xx < HW);
                    p[dy + 1][dx + 1] = ok ? d[yy * HW + xx] : 0.0f;
                }
            float gx = (p[0][0] - p[0][2]) + 2.0f * (p[1][0] - p[1][2]) + (p[2][0] - p[2][2]);
            float gy = (p[0][0] - p[2][0]) + 2.0f * (p[0][1] - p[2][1]) + (p[0][2] - p[2][2]);
            float g = sqrtf(gx * gx + gy * gy + 1e-8f);
            if (m == 0) v0 = g; else v1 = g;
        }
    }

    // ---- Phase 2: ascending bitonic sort of the 2048-chunk ----
    // shfl for j=2..32, smem for j>=64, in-thread for j=1.
    #pragma unroll
    for (int k = 2; k <= CHUNK; k <<= 1) {
        #pragma unroll
        for (int j = k >> 1; j >= 1; j >>= 1) {
            if (j >= 64) {
                __syncthreads();
                *(float2*)&sT[i] = make_float2(v0, v1);
                __syncthreads();
                bool keepMin = ((i & j) == 0) == ((i & k) == 0);
                float2 o = *(float2*)&sT[i ^ j];
                v0 = keepMin ? fminf(v0, o.x) : fmaxf(v0, o.x);
                v1 = keepMin ? fminf(v1, o.y) : fmaxf(v1, o.y);
            } else if (j >= 2) {
                bool keepMin = ((i & j) == 0) == ((i & k) == 0);
                float o0 = __shfl_xor_sync(0xffffffffu, v0, j >> 1);
                float o1 = __shfl_xor_sync(0xffffffffu, v1, j >> 1);
                v0 = keepMin ? fminf(v0, o0) : fmaxf(v0, o0);
                v1 = keepMin ? fminf(v1, o1) : fmaxf(v1, o1);
            } else {
                bool up = ((i & k) == 0);
                float lo = fminf(v0, v1), hi = fmaxf(v0, v1);
                v0 = up ? lo : hi;
                v1 = up ? hi : lo;
            }
        }
    }

    // publish sorted chunk
    *(float2*)(g_scr + (b * 2 + arr) * NP + e0) = make_float2(v0, v1);

    // ---- Phase 3: grid barrier (ticket-based, replay-safe) ----
    __syncthreads();                   // all smem sort traffic done, stores issued
    if (t == 0) {
        __threadfence();               // g_scr writes visible before arrival
        unsigned int ticket = atomicAdd(&g_bar, 1u);
        unsigned int target = (ticket / nblk + 1u) * nblk;
        while (*(volatile unsigned int*)&g_bar < target) { }
    }
    __syncthreads();
    __threadfence();                   // acquire side before reading peers' g_scr

    // ---- Phase 4: load other array's sorted chunks, search own queries ----
    const float* tgt = g_scr + (b * 2 + (arr ^ 1)) * NP;
    ((float4*)sT)[t] = ((const float4*)tgt)[t];   // 4096 floats, float4 per thread
    __syncthreads();

    float acc = 0.0f;
    #pragma unroll
    for (int m = 0; m < 2; m++) {
        float x = m ? v1 : v0;         // this thread's sorted queries (registers)
        float dmin = 3.4e38f;
        #pragma unroll
        for (int ch = 0; ch < 2; ch++) {
            const float* T = sT + ch * CHUNK;
            int pos = 0;               // branchless lower_bound, saturates at CHUNK-1
            #pragma unroll
            for (int s = CHUNK / 2; s >= 1; s >>= 1) {
                if (T[pos + s - 1] < x) pos += s;
            }
            // if x > all: pos=CHUNK-1, T[pos]<x, fabsf = distance to chunk max
            float dd = fabsf(T[pos] - x);
            if (pos > 0) dd = fminf(dd, x - T[pos - 1]);
            dmin = fminf(dmin, dd);
        }
        acc += dmin;
    }

    // ---- Phase 5: reduce + accumulate ----
    #pragma unroll
    for (int o = 16; o > 0; o >>= 1) acc += __shfl_xor_sync(0xffffffffu, acc, o);
    if ((t & 31) == 0) swarp[t >> 5] = acc;
    __syncthreads();
    if (t < 32) {
        float z = swarp[t];            // exactly 32 warps
        #pragma unroll
        for (int o = 16; o > 0; o >>= 1) z += __shfl_xor_sync(0xffffffffu, z, o);
        if (t == 0) atomicAdd(out, z * inv_total);
    }
}

extern "C" void kernel_launch(void* const* d_in, const int* in_sizes, int n_in,
                              void* d_out, int out_size) {
    const float* depth = (const float*)d_in[0];
    const float* bnd   = (const float*)d_in[1];
    float* out = (float*)d_out;

    int B = in_sizes[0] / NP;
    if (B > MAXB) B = MAXB;
    float inv_total = 1.0f / (float)(B * NP);

    chamfer_fused_kernel<<<B * 4, 1024>>>(depth, bnd, out, inv_total);
}